// round 1
// baseline (speedup 1.0000x reference)
#include <cuda_runtime.h>

// Problem constants
#define N_ITEMS 20000
#define N_REC   8
#define N_USERS 2048
#define U4      (N_USERS / 4)          // 512 float4 columns
#define ITEMS_PER_BLOCK 40             // gridDim.y = 500

// Scratch: per-user column max (as float bits) and reciprocal.
__device__ float g_max[N_USERS];
__device__ float g_inv[N_USERS];

__global__ void init_max_kernel() {
    int u = blockIdx.x * blockDim.x + threadIdx.x;
    if (u < N_USERS) g_max[u] = 0.0f;
}

// Pass 1: scores[i][u] = sum_r input[i*8+r][u] * w[r]; write scores to d_out,
// accumulate per-column max via atomicMax on float bits (all values >= 0).
__global__ void __launch_bounds__(256) score_max_kernel(
    const float4* __restrict__ in,   // [N_ITEMS*N_REC, U4]
    const float*  __restrict__ w,    // [8]
    float4*       __restrict__ scores)  // [N_ITEMS, U4]
{
    const int u4 = blockIdx.x * blockDim.x + threadIdx.x;   // 0..511 (gridDim.x=2, blockDim=256)
    if (u4 >= U4) return;

    float wr[N_REC];
#pragma unroll
    for (int r = 0; r < N_REC; ++r) wr[r] = __ldg(&w[r]);

    const int i0   = blockIdx.y * ITEMS_PER_BLOCK;
    const int iend = min(i0 + ITEMS_PER_BLOCK, N_ITEMS);

    float mx = 0.f, my = 0.f, mz = 0.f, mw = 0.f;

    for (int i = i0; i < iend; ++i) {
        const float4* row = in + (size_t)i * N_REC * U4 + u4;
        float sx = 0.f, sy = 0.f, sz = 0.f, sw = 0.f;
#pragma unroll
        for (int r = 0; r < N_REC; ++r) {
            float4 v = __ldg(row + (size_t)r * U4);
            sx = fmaf(v.x, wr[r], sx);
            sy = fmaf(v.y, wr[r], sy);
            sz = fmaf(v.z, wr[r], sz);
            sw = fmaf(v.w, wr[r], sw);
        }
        float4 s = make_float4(sx, sy, sz, sw);
        scores[(size_t)i * U4 + u4] = s;
        mx = fmaxf(mx, sx);
        my = fmaxf(my, sy);
        mz = fmaxf(mz, sz);
        mw = fmaxf(mw, sw);
    }

    // Non-negative floats: int bit-pattern ordering == float ordering.
    int* gm = (int*)g_max;
    atomicMax(&gm[u4 * 4 + 0], __float_as_int(mx));
    atomicMax(&gm[u4 * 4 + 1], __float_as_int(my));
    atomicMax(&gm[u4 * 4 + 2], __float_as_int(mz));
    atomicMax(&gm[u4 * 4 + 3], __float_as_int(mw));
}

__global__ void recip_kernel() {
    int u = blockIdx.x * blockDim.x + threadIdx.x;
    if (u < N_USERS) g_inv[u] = 1.0f / g_max[u];
}

// Pass 2: out = scores * inv_max (in place on d_out).
__global__ void __launch_bounds__(256) normalize_kernel(float4* __restrict__ scores)
{
    int idx = blockIdx.x * blockDim.x + threadIdx.x;   // over N_ITEMS*U4
    if (idx >= N_ITEMS * U4) return;
    int u4 = idx & (U4 - 1);                            // U4 = 512 (pow2)
    float4 s   = scores[idx];
    float4 inv = *((const float4*)g_inv + u4);
    s.x *= inv.x; s.y *= inv.y; s.z *= inv.z; s.w *= inv.w;
    scores[idx] = s;
}

extern "C" void kernel_launch(void* const* d_in, const int* in_sizes, int n_in,
                              void* d_out, int out_size)
{
    const float4* in = (const float4*)d_in[0];   // input [160000, 2048] f32
    const float*  w  = (const float*)d_in[1];    // w [1, 8] f32
    float4* scores = (float4*)d_out;             // [20000, 2048] f32

    // Reset per-run state (graph replays must be deterministic).
    init_max_kernel<<<(N_USERS + 255) / 256, 256>>>();

    dim3 grid1(U4 / 256, (N_ITEMS + ITEMS_PER_BLOCK - 1) / ITEMS_PER_BLOCK);
    score_max_kernel<<<grid1, 256>>>(in, w, scores);

    recip_kernel<<<(N_USERS + 255) / 256, 256>>>();

    int total4 = N_ITEMS * U4;                   // 10,240,000
    normalize_kernel<<<(total4 + 255) / 256, 256>>>(scores);
}